// round 15
// baseline (speedup 1.0000x reference)
#include <cuda_runtime.h>
#include <cuda_fp16.h>

// ---------------------------------------------------------------------------
// SSIM loss, single fused kernel, fp16 (half2) blur pipeline, CENTERED s.
// s' = p+t-1 (zero-mean!), d = p-t; blur {s', d, s'^2, d^2} in half2 pairs:
// every conv step is one HFMA2. Variance is shift-invariant:
//   vs = blur(s'^2) - mu_s'^2 (>=0), vd = blur(d^2) - mu_d^2 (>=0)
//   mu_s = mu_s' + 1 (luminance terms only):
//   4*mu_pt = mu_s^2 - mu_d^2          2*(mu_p^2+mu_t^2) = mu_s^2 + mu_d^2
//   4*sigma_pt = vs - vd               2*(sig_p^2+sig_t^2) = vs + vd
// Centering makes blur(s'^2) ~ 0.25 instead of ~1.3, cutting the fp16
// cancellation error in vs by ~5x (rel_err ~1.5e-4, safely under 1e-3).
// Tile 32x54, 256 threads, halo 64 x 44 (x start 32*bx-6 even -> aligned
// float2 gmem loads). h-pass: 64 rows x 4 spans = 256 items, one per thread.
// v-pass: 8 warps x 7 rows (clamped row index, excess masked).
// smem 28.4 KB, low regs -> 5 blocks/SM. Last block finalizes.
// ---------------------------------------------------------------------------

#define T    256
#define TW   32
#define TH   54
#define INW  44
#define INH  64
#define SPITCH 45   // half2 (4B) units, odd -> conflict-free h-pass loads
#define HPITCH 33   // uint2 (8B) units, odd -> conflict-free v-pass loads
#define SMEM_IN_BYTES (INH * SPITCH * 4)     // 11520
#define SMEM_H_BYTES  (INH * HPITCH * 8)     // 16896
#define SMEM_BYTES    (SMEM_IN_BYTES + SMEM_H_BYTES)   // 28416

#define GW_INIT { \
    0.00102840f, 0.00759879f, 0.03600075f, 0.10936067f, 0.21300550f, \
    0.26601167f, \
    0.21300550f, 0.10936067f, 0.03600075f, 0.00759879f, 0.00102840f }

__device__ __forceinline__ unsigned h2_as_u32(__half2 h) {
    return *reinterpret_cast<unsigned*>(&h);
}
__device__ __forceinline__ __half2 u32_as_h2(unsigned u) {
    return *reinterpret_cast<__half2*>(&u);
}

__device__ double g_sum;
__device__ unsigned int g_count;

__global__ __launch_bounds__(T, 5) void ssim_kernel(
    const float* __restrict__ pred, const float* __restrict__ tgt,
    float* __restrict__ out, float inv_n, unsigned int nblocks)
{
    constexpr float GW[11] = GW_INIT;

    extern __shared__ char smem_raw[];
    __half2* s_in = (__half2*)smem_raw;                       // [INH][SPITCH]
    uint2*   s_h  = (uint2*)(smem_raw + SMEM_IN_BYTES);       // [INH][HPITCH]
    __shared__ float s_wsum[8];

    const int tid = threadIdx.x;
    const int gxh = blockIdx.x * TW - 6;       // halo x start (even!)
    const int gy0 = blockIdx.y * TH - 5;
    const size_t po = (size_t)blockIdx.z << 18;               // * 512*512
    const float* pbase = pred + po;
    const float* tbase = tgt + po;

    // ---- load halo (64 x 44) as aligned float2; pack (s-1, d) in fp16 ----
    // NOTE on zero padding: outside the image the reference uses p=t=0, i.e.
    // s=0 -> s'= -1. We must pack s'=-1 there, which p=t=0 below produces.
    {
        // 64 rows x 22 pairs = 1408 items; step 256 = 11*22 + 14
        int r  = tid / 22;          // one division total
        int c2 = tid - r * 22;
        #pragma unroll
        for (int ii = 0; ii < 6; ii++) {
            if (r < INH) {
                int gy  = gy0 + r;
                int gxp = gxh + c2 * 2;        // even; pair all-in or all-out
                float2 p = make_float2(0.0f, 0.0f);
                float2 t = make_float2(0.0f, 0.0f);
                if ((unsigned)gy < 512u && (unsigned)gxp < 512u) {
                    int g = (gy << 9) + gxp;
                    p = *(const float2*)(pbase + g);
                    t = *(const float2*)(tbase + g);
                }
                __half2* dst = s_in + r * SPITCH + c2 * 2;
                dst[0] = __floats2half2_rn(p.x + t.x - 1.0f, p.x - t.x);
                dst[1] = __floats2half2_rn(p.y + t.y - 1.0f, p.y - t.y);
            }
            r += 11; c2 += 14;
            if (c2 >= 22) { c2 -= 22; r += 1; }
        }
    }
    __syncthreads();

    // ---- packed fp16 weights: 6 unique registers (Gaussian symmetry) ----
    __half2 W[6];
    #pragma unroll
    for (int w = 0; w < 6; w++) W[w] = __floats2half2_rn(GW[w], GW[w]);
    #define WSYM(w) W[(w) < 6 ? (w) : 10 - (w)]

    // ---- horizontal 11-tap pass: exactly one 8-wide item per thread ----
    {
        const int row  = tid & (INH - 1);   // consecutive tids -> rows
        const int span = tid >> 6;          // 0..3
        const int c0   = span * 8;

        __half2 a01[8], a23[8];
        #pragma unroll
        for (int j = 0; j < 8; j++) {
            a01[j] = __floats2half2_rn(0.f, 0.f);
            a23[j] = __floats2half2_rn(0.f, 0.f);
        }

        // output x = 32bx + c0 + j needs halo cols (c0 + j + 1)..(c0 + j + 11)
        const __half2* rowp = s_in + row * SPITCH + c0;
        #pragma unroll
        for (int k = 1; k <= 18; k++) {
            __half2 v  = rowp[k];          // (s', d)
            __half2 sq = __hmul2(v, v);    // (s'^2, d^2)
            #pragma unroll
            for (int j = 0; j < 8; j++) {
                const int w = k - 1 - j;
                if (w >= 0 && w < 11) {
                    a01[j] = __hfma2(WSYM(w), v,  a01[j]);
                    a23[j] = __hfma2(WSYM(w), sq, a23[j]);
                }
            }
        }
        uint2* hrow = s_h + row * HPITCH + c0;
        #pragma unroll
        for (int j = 0; j < 8; j++)
            hrow[j] = make_uint2(h2_as_u32(a01[j]), h2_as_u32(a23[j]));
    }
    __syncthreads();

    // ---- vertical 11-tap pass: warp w -> rows 7w..7w+6, col = lane ----
    const int col  = tid & 31;
    const int row0 = (tid >> 5) * 7;

    __half2 m01[7], m23[7];
    #pragma unroll
    for (int o = 0; o < 7; o++) {
        m01[o] = __floats2half2_rn(0.f, 0.f);
        m23[o] = __floats2half2_rn(0.f, 0.f);
    }

    #pragma unroll
    for (int i = 0; i < 17; i++) {
        int ri = row0 + i;
        ri = ri > INH - 1 ? INH - 1 : ri;   // clamp (excess rows masked below)
        uint2 hv = s_h[ri * HPITCH + col];
        __half2 h01 = u32_as_h2(hv.x);
        __half2 h23 = u32_as_h2(hv.y);
        #pragma unroll
        for (int o = 0; o < 7; o++) {
            const int w = i - o;
            if (w >= 0 && w < 11) {
                m01[o] = __hfma2(WSYM(w), h01, m01[o]);
                m23[o] = __hfma2(WSYM(w), h23, m23[o]);
            }
        }
    }

    // ---- SSIM map in fp32 (num & den both scaled by 4); mask invalid rows ----
    const int gyout = blockIdx.y * TH + row0;
    float local = 0.0f;
    #pragma unroll
    for (int o = 0; o < 7; o++) {
        float2 f01 = __half22float2(m01[o]);   // (mu_s', mu_d)
        float2 f23 = __half22float2(m23[o]);   // (blur s'^2, blur d^2)
        float mus  = f01.x + 1.0f;             // mu_s (luminance)
        float mus2 = mus * mus;
        float mud2 = f01.y * f01.y;
        float vs = fmaxf(f23.x - f01.x * f01.x, 0.0f);   // var: centered!
        float vd = fmaxf(f23.y - mud2, 0.0f);
        float num = (mus2 - mud2 + 2e-4f) * (vs - vd + 18e-4f);
        float den = (mus2 + mud2 + 2e-4f) * (vs + vd + 18e-4f);
        float v = __fdividef(num, den);
        if (row0 + o < TH && gyout + o < 512) local += v;
    }

    // ---- block reduction ----
    #pragma unroll
    for (int off = 16; off; off >>= 1)
        local += __shfl_xor_sync(0xffffffffu, local, off);
    if ((tid & 31) == 0) s_wsum[tid >> 5] = local;
    __syncthreads();

    if (tid == 0) {
        float bs = 0.0f;
        #pragma unroll
        for (int i = 0; i < 8; i++) bs += s_wsum[i];
        atomicAdd(&g_sum, (double)bs);
        __threadfence();
        unsigned int done = atomicAdd(&g_count, 1u) + 1u;
        if (done == nblocks) {
            unsigned long long raw =
                atomicExch((unsigned long long*)&g_sum, 0ULL);
            out[0] = 1.0f - (float)__longlong_as_double(raw) * inv_n;
            atomicExch(&g_count, 0u);
        }
    }
}

extern "C" void kernel_launch(void* const* d_in, const int* in_sizes, int n_in,
                              void* d_out, int out_size)
{
    const float* pred = (const float*)d_in[0];
    const float* tgt  = (const float*)d_in[1];
    float* out = (float*)d_out;

    const int n_elems = in_sizes[0];
    const int planes  = n_elems >> 18;

    cudaFuncSetAttribute(ssim_kernel,
                         cudaFuncAttributeMaxDynamicSharedMemorySize,
                         SMEM_BYTES);

    dim3 grid(512 / TW, (512 + TH - 1) / TH, planes);
    unsigned int nblocks = grid.x * grid.y * grid.z;
    ssim_kernel<<<grid, T, SMEM_BYTES>>>(pred, tgt, out,
                                         1.0f / (float)n_elems, nblocks);
}

// round 16
// speedup vs baseline: 1.0030x; 1.0030x over previous
#include <cuda_runtime.h>
#include <cuda_fp16.h>

// ---------------------------------------------------------------------------
// SSIM loss, single fused kernel, fp16 (half2) blur pipeline, CENTERED s.
// s' = p+t-1 (zero-mean), d = p-t; blur {s', d, s'^2, d^2} in half2 pairs:
// every conv step is one HFMA2. Variance is shift-invariant:
//   vs = blur(s'^2) - mu_s'^2 (>=0), vd = blur(d^2) - mu_d^2 (>=0)
//   mu_s = mu_s' + 1 (luminance only):
//   4*mu_pt = mu_s^2 - mu_d^2          2*(mu_p^2+mu_t^2) = mu_s^2 + mu_d^2
//   4*sigma_pt = vs - vd               2*(sig_p^2+sig_t^2) = vs + vd
// Tile 32x54, 256 threads, halo 64 x 44 (x start 32*bx-6 even -> aligned
// float2 gmem loads). h-pass: 64 rows x 4 spans = 256 items, one per thread.
// v-pass: 8 warps x 7 rows, NO clamp: s_h is padded to 74 rows so reads
// row0..row0+16 <= 65 are always in-bounds; garbage rows only reach outputs
// that are masked from the sum. All v-pass LDS offsets are immediates.
// smem 31 KB, low regs -> 5 blocks/SM. Last block finalizes.
// ---------------------------------------------------------------------------

#define T    256
#define TW   32
#define TH   54
#define INW  44
#define INH  64
#define HROWS (INH + 10)   // padded: v-pass reads up to row 65 unclamped
#define SPITCH 45   // half2 (4B) units, odd -> conflict-free h-pass loads
#define HPITCH 33   // uint2 (8B) units, odd -> conflict-free v-pass loads
#define SMEM_IN_BYTES (INH * SPITCH * 4)       // 11520
#define SMEM_H_BYTES  (HROWS * HPITCH * 8)     // 19536
#define SMEM_BYTES    (SMEM_IN_BYTES + SMEM_H_BYTES)   // 31056

#define GW_INIT { \
    0.00102840f, 0.00759879f, 0.03600075f, 0.10936067f, 0.21300550f, \
    0.26601167f, \
    0.21300550f, 0.10936067f, 0.03600075f, 0.00759879f, 0.00102840f }

__device__ __forceinline__ unsigned h2_as_u32(__half2 h) {
    return *reinterpret_cast<unsigned*>(&h);
}
__device__ __forceinline__ __half2 u32_as_h2(unsigned u) {
    return *reinterpret_cast<__half2*>(&u);
}

__device__ double g_sum;
__device__ unsigned int g_count;

__global__ __launch_bounds__(T, 5) void ssim_kernel(
    const float* __restrict__ pred, const float* __restrict__ tgt,
    float* __restrict__ out, float inv_n, unsigned int nblocks)
{
    constexpr float GW[11] = GW_INIT;

    extern __shared__ char smem_raw[];
    __half2* s_in = (__half2*)smem_raw;                       // [INH][SPITCH]
    uint2*   s_h  = (uint2*)(smem_raw + SMEM_IN_BYTES);       // [HROWS][HPITCH]
    __shared__ float s_wsum[8];

    const int tid = threadIdx.x;
    const int gxh = blockIdx.x * TW - 6;       // halo x start (even!)
    const int gy0 = blockIdx.y * TH - 5;
    const size_t po = (size_t)blockIdx.z << 18;               // * 512*512
    const float* pbase = pred + po;
    const float* tbase = tgt + po;

    // ---- load halo (64 x 44) as aligned float2; pack (s-1, d) in fp16 ----
    // Outside the image the reference zero-pads: p=t=0 -> s'=-1, d=0, which
    // the default p=t=0 below produces.
    {
        // 64 rows x 22 pairs = 1408 items; step 256 = 11*22 + 14
        int r  = tid / 22;          // one division total
        int c2 = tid - r * 22;
        #pragma unroll
        for (int ii = 0; ii < 6; ii++) {
            if (r < INH) {
                int gy  = gy0 + r;
                int gxp = gxh + c2 * 2;        // even; pair all-in or all-out
                float2 p = make_float2(0.0f, 0.0f);
                float2 t = make_float2(0.0f, 0.0f);
                if ((unsigned)gy < 512u && (unsigned)gxp < 512u) {
                    int g = (gy << 9) + gxp;
                    p = *(const float2*)(pbase + g);
                    t = *(const float2*)(tbase + g);
                }
                __half2* dst = s_in + r * SPITCH + c2 * 2;
                dst[0] = __floats2half2_rn(p.x + t.x - 1.0f, p.x - t.x);
                dst[1] = __floats2half2_rn(p.y + t.y - 1.0f, p.y - t.y);
            }
            r += 11; c2 += 14;
            if (c2 >= 22) { c2 -= 22; r += 1; }
        }
    }
    __syncthreads();

    // ---- packed fp16 weights: 6 unique registers (Gaussian symmetry) ----
    __half2 W[6];
    #pragma unroll
    for (int w = 0; w < 6; w++) W[w] = __floats2half2_rn(GW[w], GW[w]);
    #define WSYM(w) W[(w) < 6 ? (w) : 10 - (w)]

    // ---- horizontal 11-tap pass: exactly one 8-wide item per thread ----
    {
        const int row  = tid & (INH - 1);   // consecutive tids -> rows
        const int span = tid >> 6;          // 0..3
        const int c0   = span * 8;

        __half2 a01[8], a23[8];
        #pragma unroll
        for (int j = 0; j < 8; j++) {
            a01[j] = __floats2half2_rn(0.f, 0.f);
            a23[j] = __floats2half2_rn(0.f, 0.f);
        }

        // output x = 32bx + c0 + j needs halo cols (c0 + j + 1)..(c0 + j + 11)
        const __half2* rowp = s_in + row * SPITCH + c0;
        #pragma unroll
        for (int k = 1; k <= 18; k++) {
            __half2 v  = rowp[k];          // (s', d)
            __half2 sq = __hmul2(v, v);    // (s'^2, d^2)
            #pragma unroll
            for (int j = 0; j < 8; j++) {
                const int w = k - 1 - j;
                if (w >= 0 && w < 11) {
                    a01[j] = __hfma2(WSYM(w), v,  a01[j]);
                    a23[j] = __hfma2(WSYM(w), sq, a23[j]);
                }
            }
        }
        uint2* hrow = s_h + row * HPITCH + c0;
        #pragma unroll
        for (int j = 0; j < 8; j++)
            hrow[j] = make_uint2(h2_as_u32(a01[j]), h2_as_u32(a23[j]));
    }
    __syncthreads();

    // ---- vertical 11-tap pass: warp w -> rows 7w..7w+6, col = lane ----
    // No clamp: s_h rows [INH, HROWS) are uninitialized garbage, read only
    // for outputs masked out of the sum below. All offsets are immediates.
    const int col  = tid & 31;
    const int row0 = (tid >> 5) * 7;

    __half2 m01[7], m23[7];
    #pragma unroll
    for (int o = 0; o < 7; o++) {
        m01[o] = __floats2half2_rn(0.f, 0.f);
        m23[o] = __floats2half2_rn(0.f, 0.f);
    }

    const uint2* hcol = s_h + row0 * HPITCH + col;
    #pragma unroll
    for (int i = 0; i < 17; i++) {
        uint2 hv = hcol[i * HPITCH];       // imm offset; rows <= 65 < 74
        __half2 h01 = u32_as_h2(hv.x);
        __half2 h23 = u32_as_h2(hv.y);
        #pragma unroll
        for (int o = 0; o < 7; o++) {
            const int w = i - o;
            if (w >= 0 && w < 11) {
                m01[o] = __hfma2(WSYM(w), h01, m01[o]);
                m23[o] = __hfma2(WSYM(w), h23, m23[o]);
            }
        }
    }

    // ---- SSIM map in fp32 (num & den both scaled by 4); mask invalid rows ----
    const int gyout = blockIdx.y * TH + row0;
    float local = 0.0f;
    #pragma unroll
    for (int o = 0; o < 7; o++) {
        float2 f01 = __half22float2(m01[o]);   // (mu_s', mu_d)
        float2 f23 = __half22float2(m23[o]);   // (blur s'^2, blur d^2)
        float mus  = f01.x + 1.0f;             // mu_s (luminance)
        float mus2 = mus * mus;
        float mud2 = f01.y * f01.y;
        float vs = fmaxf(f23.x - f01.x * f01.x, 0.0f);   // centered variance
        float vd = fmaxf(f23.y - mud2, 0.0f);
        float num = (mus2 - mud2 + 2e-4f) * (vs - vd + 18e-4f);
        float den = (mus2 + mud2 + 2e-4f) * (vs + vd + 18e-4f);
        float v = __fdividef(num, den);
        if (row0 + o < TH && gyout + o < 512) local += v;
    }

    // ---- block reduction ----
    #pragma unroll
    for (int off = 16; off; off >>= 1)
        local += __shfl_xor_sync(0xffffffffu, local, off);
    if ((tid & 31) == 0) s_wsum[tid >> 5] = local;
    __syncthreads();

    if (tid == 0) {
        float bs = 0.0f;
        #pragma unroll
        for (int i = 0; i < 8; i++) bs += s_wsum[i];
        atomicAdd(&g_sum, (double)bs);
        __threadfence();
        unsigned int done = atomicAdd(&g_count, 1u) + 1u;
        if (done == nblocks) {
            unsigned long long raw =
                atomicExch((unsigned long long*)&g_sum, 0ULL);
            out[0] = 1.0f - (float)__longlong_as_double(raw) * inv_n;
            atomicExch(&g_count, 0u);
        }
    }
}

extern "C" void kernel_launch(void* const* d_in, const int* in_sizes, int n_in,
                              void* d_out, int out_size)
{
    const float* pred = (const float*)d_in[0];
    const float* tgt  = (const float*)d_in[1];
    float* out = (float*)d_out;

    const int n_elems = in_sizes[0];
    const int planes  = n_elems >> 18;

    cudaFuncSetAttribute(ssim_kernel,
                         cudaFuncAttributeMaxDynamicSharedMemorySize,
                         SMEM_BYTES);

    dim3 grid(512 / TW, (512 + TH - 1) / TH, planes);
    unsigned int nblocks = grid.x * grid.y * grid.z;
    ssim_kernel<<<grid, T, SMEM_BYTES>>>(pred, tgt, out,
                                         1.0f / (float)n_elems, nblocks);
}